// round 5
// baseline (speedup 1.0000x reference)
#include <cuda_runtime.h>

#define NB   32
#define CIN  240
#define HH   56
#define WW   56
#define HW   3136
#define MID  120
#define COUT 480
#define GRP  3
#define GIN  80    // Cin / G
#define GMID 40    // mid / G
#define GOUT 160   // Cout / G

// Scratch (allocation-free rule: __device__ globals)
__device__ float g_y1[NB * MID * HW];   // conv1 output (post BN+ReLU)
__device__ float g_y2[NB * MID * HW];   // dw output, SHUFFLED channel order
// Pre-packed tf32 A-fragments (mma.m16n8k8 per-lane layout), BN scale FOLDED IN
__device__ uint4 g_wscf[28800];
__device__ uint4 g_w3f[4800];

static __device__ __forceinline__ unsigned cvt_tf32(float f) {
    unsigned u; asm("cvt.rna.tf32.f32 %0, %1;" : "=r"(u) : "f"(f)); return u;
}

static __device__ __forceinline__ void mma_tf32(float c[4], const unsigned a[4],
                                                const unsigned b[2]) {
    asm volatile(
        "mma.sync.aligned.m16n8k8.row.col.f32.tf32.tf32.f32 "
        "{%0,%1,%2,%3}, {%4,%5,%6,%7}, {%8,%9}, {%0,%1,%2,%3};"
        : "+f"(c[0]), "+f"(c[1]), "+f"(c[2]), "+f"(c[3])
        : "r"(a[0]), "r"(a[1]), "r"(a[2]), "r"(a[3]), "r"(b[0]), "r"(b[1]));
}

static __device__ __forceinline__ unsigned smem_u32(const void* p) {
    return (unsigned)__cvta_generic_to_shared(p);
}
#define CP16(dst, src) \
    asm volatile("cp.async.cg.shared.global [%0], [%1], 16;" :: "r"(dst), "l"(src))
#define CP_COMMIT() asm volatile("cp.async.commit_group;")
#define CP_WAIT0()  asm volatile("cp.async.wait_group 0;")

// ---------------------------------------------------------------------------
// prep: repack wsc/w3 into per-lane tf32 A-fragments with BN scales folded in.
// ---------------------------------------------------------------------------
__global__ void prep_w(const float* __restrict__ wsc, const float* __restrict__ w3,
                       const float* __restrict__ scale_sc, const float* __restrict__ scale3)
{
    int idx = blockIdx.x * 256 + threadIdx.x;
    if (idx < 28800) {
        int lane = idx & 31; int r = idx >> 5;
        int mt = r % 10; r /= 10;
        int kq = r % 5;  r /= 5;
        int kc = r % 6;  int ct = r / 6;
        int gid = lane >> 2, tig = lane & 3;
        int row = ct * GOUT + mt * 16 + gid;
        int col = kc * 40 + kq * 8 + tig;
        float sa = scale_sc[row], sb = scale_sc[row + 8];
        uint4 v;
        v.x = cvt_tf32(wsc[row * CIN + col] * sa);
        v.y = cvt_tf32(wsc[(row + 8) * CIN + col] * sb);
        v.z = cvt_tf32(wsc[row * CIN + col + 4] * sa);
        v.w = cvt_tf32(wsc[(row + 8) * CIN + col + 4] * sb);
        g_wscf[idx] = v;
    } else if (idx < 28800 + 4800) {
        int i2 = idx - 28800;
        int lane = i2 & 31; int r = i2 >> 5;
        int mt = r % 10; r /= 10;
        int kq = r % 5;  int ct = r / 5;
        int gid = lane >> 2, tig = lane & 3;
        int row = ct * GOUT + mt * 16 + gid;
        int col = kq * 8 + tig;
        float sa = scale3[row], sb = scale3[row + 8];
        uint4 v;
        v.x = cvt_tf32(w3[row * GMID + col] * sa);
        v.y = cvt_tf32(w3[(row + 8) * GMID + col] * sb);
        v.z = cvt_tf32(w3[row * GMID + col + 4] * sa);
        v.w = cvt_tf32(w3[(row + 8) * GMID + col + 4] * sb);
        g_w3f[i2] = v;
    }
}

// ---------------------------------------------------------------------------
// K1: grouped 1x1 conv + BN + ReLU -> g_y1 (fp32 scalar)
// 128 thr; warp = 10 m-rows x 64 px (2 px regs amortize weight loads).
// ---------------------------------------------------------------------------
__global__ __launch_bounds__(128) void k1_conv1(
    const float* __restrict__ x, const float* __restrict__ w1,
    const float* __restrict__ scale1, const float* __restrict__ shift1)
{
    const int tile = blockIdx.x, g = blockIdx.y, n = blockIdx.z;
    const int tid = threadIdx.x, lane = tid & 31, wm4 = tid >> 5;

    __shared__ float xs[GIN][64];
    __shared__ float wt2[GIN][48];

    const float4* x4 = reinterpret_cast<const float4*>(
        x + ((size_t)n * CIN + g * GIN) * HW + tile * 64);
    for (int i = tid; i < GIN * 16; i += 128) {
        int c = i >> 4, q = i & 15;
        reinterpret_cast<float4*>(xs[c])[q] = x4[c * (HW / 4) + q];
    }
    for (int i = tid; i < GIN * GMID; i += 128) {
        int k = i % GIN, mi = i / GIN;
        wt2[k][(mi / 10) * 12 + (mi % 10)] = w1[(g * GMID + mi) * GIN + k];
    }
    __syncthreads();

    float acc[10][2] = {};
    #pragma unroll 2
    for (int k = 0; k < GIN; k++) {
        float b0 = xs[k][lane], b1 = xs[k][lane + 32];
        const float* wr = &wt2[k][wm4 * 12];
        float4 wa = *reinterpret_cast<const float4*>(wr);
        float4 wb = *reinterpret_cast<const float4*>(wr + 4);
        float2 wc = *reinterpret_cast<const float2*>(wr + 8);
        acc[0][0] = fmaf(wa.x, b0, acc[0][0]); acc[0][1] = fmaf(wa.x, b1, acc[0][1]);
        acc[1][0] = fmaf(wa.y, b0, acc[1][0]); acc[1][1] = fmaf(wa.y, b1, acc[1][1]);
        acc[2][0] = fmaf(wa.z, b0, acc[2][0]); acc[2][1] = fmaf(wa.z, b1, acc[2][1]);
        acc[3][0] = fmaf(wa.w, b0, acc[3][0]); acc[3][1] = fmaf(wa.w, b1, acc[3][1]);
        acc[4][0] = fmaf(wb.x, b0, acc[4][0]); acc[4][1] = fmaf(wb.x, b1, acc[4][1]);
        acc[5][0] = fmaf(wb.y, b0, acc[5][0]); acc[5][1] = fmaf(wb.y, b1, acc[5][1]);
        acc[6][0] = fmaf(wb.z, b0, acc[6][0]); acc[6][1] = fmaf(wb.z, b1, acc[6][1]);
        acc[7][0] = fmaf(wb.w, b0, acc[7][0]); acc[7][1] = fmaf(wb.w, b1, acc[7][1]);
        acc[8][0] = fmaf(wc.x, b0, acc[8][0]); acc[8][1] = fmaf(wc.x, b1, acc[8][1]);
        acc[9][0] = fmaf(wc.y, b0, acc[9][0]); acc[9][1] = fmaf(wc.y, b1, acc[9][1]);
    }

    float* yp = g_y1 + (size_t)n * MID * HW + tile * 64;
    #pragma unroll
    for (int j = 0; j < 10; j++) {
        int mg = g * GMID + wm4 * 10 + j;
        float s = scale1[mg], sh = shift1[mg];
        yp[(size_t)mg * HW + lane]      = fmaxf(fmaf(acc[j][0], s, sh), 0.f);
        yp[(size_t)mg * HW + lane + 32] = fmaxf(fmaf(acc[j][1], s, sh), 0.f);
    }
}

// ---------------------------------------------------------------------------
// K2: depthwise 3x3 (pad 1) + BN, channel-shuffled write -> g_y2
// 4 outputs per thread along w (float4 I/O).
// ---------------------------------------------------------------------------
__global__ __launch_bounds__(256) void k2_dw(
    const float* __restrict__ w2, const float* __restrict__ scale2,
    const float* __restrict__ shift2)
{
    int idx = blockIdx.x * 256 + threadIdx.x;   // NB*MID*784 threads exactly
    int q  = idx % 784;
    int nm = idx / 784;
    int m  = nm % MID, n = nm / MID;
    int w0 = (q * 4) % WW, h = (q * 4) / WW;

    const float* p = g_y1 + (size_t)nm * HW + h * WW + w0;
    float l[3][6];
    #pragma unroll
    for (int r = 0; r < 3; r++) {
        int hh = h - 1 + r;
        if (hh >= 0 && hh < HH) {
            const float* pr = p + (r - 1) * WW;
            float4 c4 = *reinterpret_cast<const float4*>(pr);
            l[r][1] = c4.x; l[r][2] = c4.y; l[r][3] = c4.z; l[r][4] = c4.w;
            l[r][0] = (w0 > 0)       ? pr[-1] : 0.f;
            l[r][5] = (w0 + 4 < WW)  ? pr[4]  : 0.f;
        } else {
            #pragma unroll
            for (int j = 0; j < 6; j++) l[r][j] = 0.f;
        }
    }

    const float* wp = w2 + m * 9;
    float wgt[9];
    #pragma unroll
    for (int i = 0; i < 9; i++) wgt[i] = wp[i];

    float s = scale2[m], sh = shift2[m];
    float4 o;
    float* oj = &o.x;
    #pragma unroll
    for (int j = 0; j < 4; j++) {
        float a = 0.f;
        #pragma unroll
        for (int r = 0; r < 3; r++)
            #pragma unroll
            for (int d = 0; d < 3; d++)
                a = fmaf(wgt[r * 3 + d], l[r][j + d], a);
        oj[j] = fmaf(a, s, sh);
    }

    int sc = (m % GMID) * GRP + m / GMID;       // channel shuffle
    *reinterpret_cast<float4*>(g_y2 + ((size_t)n * MID + sc) * HW + h * WW + w0) = o;
}

// ---------------------------------------------------------------------------
// K3: tf32 MMA, 128 thr (4 warps), warp = 5 m-tiles x 4 n-tiles (80 acc regs).
// A frags cp.async double-buffered; B tile cp.async in NATURAL fp32 layout
// (stride 72 words -> conflict-free frag LDS), fed to MMA as raw tf32 bits.
// grid (49, 3, 32). dyn smem = 74240 B, 3 CTAs/SM.
// ---------------------------------------------------------------------------
#define AW_ELEMS 1600
#define BROW 72                                     // words per B row (288 B)
#define BWORDS (GMID * BROW)                        // 2880
#define SMEM_K3 (2 * AW_ELEMS * 16 + 2 * BWORDS * 4)   // 51200 + 23040 = 74240

static __device__ __forceinline__ void cp_A(uint4* __restrict__ dst,
                                            const uint4* __restrict__ src, int tid)
{
    unsigned d = smem_u32(dst);
    #pragma unroll 2
    for (int i = tid; i < AW_ELEMS; i += 128)
        CP16(d + i * 16, src + i);
}

// B tile: 40 rows x 64 floats (16 x 16B granules per row), row stride 288 B
static __device__ __forceinline__ void cp_B(unsigned* __restrict__ dst,
                                            const float* __restrict__ src, int tid)
{
    unsigned d = smem_u32(dst);
    #pragma unroll
    for (int i = tid; i < 640; i += 128) {
        int row = i >> 4, c4 = i & 15;
        CP16(d + row * (BROW * 4) + c4 * 16, src + (size_t)row * HW + c4 * 4);
    }
}

static __device__ __forceinline__ void compute_chunk(
    const uint4* __restrict__ aw, const unsigned* __restrict__ sB,
    int wm, int wn, int lane, float acc[5][4][4])
{
    const int gid = lane >> 2, tig = lane & 3;
    #pragma unroll
    for (int kq = 0; kq < 5; kq++) {
        unsigned a[5][4];
        #pragma unroll
        for (int j = 0; j < 5; j++)
            *reinterpret_cast<uint4*>(a[j]) = aw[(kq * 10 + wm * 5 + j) * 32 + lane];
        unsigned b[4][2];
        const int kb = kq * 8 + tig;
        #pragma unroll
        for (int t = 0; t < 4; t++) {
            int col = wn * 32 + t * 8 + gid;
            b[t][0] = sB[kb * BROW + col];
            b[t][1] = sB[(kb + 4) * BROW + col];
        }
        #pragma unroll
        for (int j = 0; j < 5; j++)
            #pragma unroll
            for (int t = 0; t < 4; t++)
                mma_tf32(acc[j][t], a[j], b[t]);
    }
}

__global__ __launch_bounds__(128, 3) void k3_fused(
    const float* __restrict__ x,
    const float* __restrict__ shift3, const float* __restrict__ shift_sc,
    float* __restrict__ out)
{
    const int tile = blockIdx.x, ct = blockIdx.y, n = blockIdx.z;
    const int tid = threadIdx.x, lane = tid & 31, warp = tid >> 5;
    const int wm = warp & 1;           // m half (80 rows)
    const int wn = warp >> 1;          // 32-px half
    const int gid = lane >> 2, tig = lane & 3;

    extern __shared__ __align__(16) char smem[];
    uint4*    s_aw = reinterpret_cast<uint4*>(smem);                      // [2][1600]
    unsigned* s_B  = reinterpret_cast<unsigned*>(smem + 2 * AW_ELEMS * 16); // [2][BWORDS]

    float acc[5][4][4];
    #pragma unroll
    for (int j = 0; j < 5; j++)
        #pragma unroll
        for (int t = 0; t < 4; t++)
            #pragma unroll
            for (int c = 0; c < 4; c++) acc[j][t][c] = 0.f;

    // chunk sources: 0 = conv3 (A=g_w3f, B=g_y2), 1..6 = shortcut kc=c-1
    const uint4* a_src[7];
    const float* b_src[7];
    a_src[0] = g_w3f + (size_t)ct * 1600;
    b_src[0] = g_y2 + ((size_t)n * MID + ct * GMID) * HW + tile * 64;
    #pragma unroll
    for (int kc = 0; kc < 6; kc++) {
        a_src[1 + kc] = g_wscf + (size_t)(ct * 6 + kc) * 1600;
        b_src[1 + kc] = x + ((size_t)n * CIN + kc * 40) * HW + tile * 64;
    }

    // prologue: stage chunk 0
    cp_A(s_aw, a_src[0], tid);
    cp_B(s_B, b_src[0], tid);
    CP_COMMIT();

    #pragma unroll 1
    for (int c = 0; c < 7; c++) {
        int cb = c & 1;
        CP_WAIT0();
        __syncthreads();
        if (c < 6) {
            cp_A(s_aw + ((c + 1) & 1) * AW_ELEMS, a_src[c + 1], tid);
            cp_B(s_B + ((c + 1) & 1) * BWORDS, b_src[c + 1], tid);
            CP_COMMIT();
        }
        compute_chunk(s_aw + cb * AW_ELEMS, s_B + cb * BWORDS, wm, wn, lane, acc);
        if (c == 0) {
            // acc := relu(acc + shift3) + shift_sc ; shortcut accumulates on top
            #pragma unroll
            for (int j = 0; j < 5; j++) {
                int rb = ct * GOUT + wm * 80 + j * 16;
                int r0 = rb + gid, r1 = r0 + 8;
                float h3a = shift3[r0], hsa = shift_sc[r0];
                float h3b = shift3[r1], hsb = shift_sc[r1];
                #pragma unroll
                for (int t = 0; t < 4; t++) {
                    acc[j][t][0] = fmaxf(acc[j][t][0] + h3a, 0.f) + hsa;
                    acc[j][t][1] = fmaxf(acc[j][t][1] + h3a, 0.f) + hsa;
                    acc[j][t][2] = fmaxf(acc[j][t][2] + h3b, 0.f) + hsb;
                    acc[j][t][3] = fmaxf(acc[j][t][3] + h3b, 0.f) + hsb;
                }
            }
        }
        __syncthreads();
    }

    // epilogue
    #pragma unroll
    for (int j = 0; j < 5; j++) {
        int rb = ct * GOUT + wm * 80 + j * 16;
        int r0 = rb + gid, r1 = r0 + 8;
        #pragma unroll
        for (int t = 0; t < 4; t++) {
            int px = tile * 64 + wn * 32 + t * 8 + 2 * tig;
            float2 v0, v1;
            v0.x = acc[j][t][0]; v0.y = acc[j][t][1];
            v1.x = acc[j][t][2]; v1.y = acc[j][t][3];
            *reinterpret_cast<float2*>(out + ((size_t)n * COUT + r0) * HW + px) = v0;
            *reinterpret_cast<float2*>(out + ((size_t)n * COUT + r1) * HW + px) = v1;
        }
    }
}

// ---------------------------------------------------------------------------
extern "C" void kernel_launch(void* const* d_in, const int* in_sizes, int n_in,
                              void* d_out, int out_size)
{
    const float* x        = (const float*)d_in[0];
    const float* w1       = (const float*)d_in[1];
    const float* scale1   = (const float*)d_in[2];
    const float* shift1   = (const float*)d_in[3];
    const float* w2       = (const float*)d_in[4];
    const float* scale2   = (const float*)d_in[5];
    const float* shift2   = (const float*)d_in[6];
    const float* w3       = (const float*)d_in[7];
    const float* scale3   = (const float*)d_in[8];
    const float* shift3   = (const float*)d_in[9];
    const float* wsc      = (const float*)d_in[10];
    const float* scale_sc = (const float*)d_in[11];
    const float* shift_sc = (const float*)d_in[12];
    float* out = (float*)d_out;

    cudaFuncSetAttribute(k3_fused, cudaFuncAttributeMaxDynamicSharedMemorySize, SMEM_K3);

    prep_w<<<(28800 + 4800 + 255) / 256, 256>>>(wsc, w3, scale_sc, scale3);
    k1_conv1<<<dim3(49, 3, 32), 128>>>(x, w1, scale1, shift1);
    k2_dw<<<dim3((NB * MID * 784) / 256), 256>>>(w2, scale2, shift2);
    k3_fused<<<dim3(49, 3, 32), 128, SMEM_K3>>>(x, shift3, shift_sc, out);
}

// round 6
// speedup vs baseline: 1.2816x; 1.2816x over previous
#include <cuda_runtime.h>

#define NB   32
#define CIN  240
#define HH   56
#define WW   56
#define HW   3136
#define MID  120
#define COUT 480
#define GRP  3
#define GIN  80    // Cin / G
#define GMID 40    // mid / G
#define GOUT 160   // Cout / G

// Scratch (allocation-free rule: __device__ globals)
__device__ float g_y1[NB * MID * HW];   // conv1 output (post BN+ReLU)
__device__ float g_y2[NB * MID * HW];   // dw output, SHUFFLED channel order
// Pre-packed tf32 A-fragments (mma.m16n8k8 per-lane layout), BN scale FOLDED IN
__device__ uint4 g_wscf[28800];
__device__ uint4 g_w3f[4800];

static __device__ __forceinline__ unsigned cvt_tf32(float f) {
    unsigned u; asm("cvt.rna.tf32.f32 %0, %1;" : "=r"(u) : "f"(f)); return u;
}

static __device__ __forceinline__ void mma_tf32(float c[4], const unsigned a[4],
                                                const unsigned b[2]) {
    asm volatile(
        "mma.sync.aligned.m16n8k8.row.col.f32.tf32.tf32.f32 "
        "{%0,%1,%2,%3}, {%4,%5,%6,%7}, {%8,%9}, {%0,%1,%2,%3};"
        : "+f"(c[0]), "+f"(c[1]), "+f"(c[2]), "+f"(c[3])
        : "r"(a[0]), "r"(a[1]), "r"(a[2]), "r"(a[3]), "r"(b[0]), "r"(b[1]));
}

static __device__ __forceinline__ unsigned smem_u32(const void* p) {
    return (unsigned)__cvta_generic_to_shared(p);
}
#define CP16(dst, src) \
    asm volatile("cp.async.cg.shared.global [%0], [%1], 16;" :: "r"(dst), "l"(src))
#define CP_COMMIT() asm volatile("cp.async.commit_group;")
#define CP_WAIT0()  asm volatile("cp.async.wait_group 0;")

// ---------------------------------------------------------------------------
// prep: repack wsc/w3 into per-lane tf32 A-fragments with BN scales folded in.
// ---------------------------------------------------------------------------
__global__ void prep_w(const float* __restrict__ wsc, const float* __restrict__ w3,
                       const float* __restrict__ scale_sc, const float* __restrict__ scale3)
{
    int idx = blockIdx.x * 256 + threadIdx.x;
    if (idx < 28800) {
        int lane = idx & 31; int r = idx >> 5;
        int mt = r % 10; r /= 10;
        int kq = r % 5;  r /= 5;
        int kc = r % 6;  int ct = r / 6;
        int gid = lane >> 2, tig = lane & 3;
        int row = ct * GOUT + mt * 16 + gid;
        int col = kc * 40 + kq * 8 + tig;
        float sa = scale_sc[row], sb = scale_sc[row + 8];
        uint4 v;
        v.x = cvt_tf32(wsc[row * CIN + col] * sa);
        v.y = cvt_tf32(wsc[(row + 8) * CIN + col] * sb);
        v.z = cvt_tf32(wsc[row * CIN + col + 4] * sa);
        v.w = cvt_tf32(wsc[(row + 8) * CIN + col + 4] * sb);
        g_wscf[idx] = v;
    } else if (idx < 28800 + 4800) {
        int i2 = idx - 28800;
        int lane = i2 & 31; int r = i2 >> 5;
        int mt = r % 10; r /= 10;
        int kq = r % 5;  int ct = r / 5;
        int gid = lane >> 2, tig = lane & 3;
        int row = ct * GOUT + mt * 16 + gid;
        int col = kq * 8 + tig;
        float sa = scale3[row], sb = scale3[row + 8];
        uint4 v;
        v.x = cvt_tf32(w3[row * GMID + col] * sa);
        v.y = cvt_tf32(w3[(row + 8) * GMID + col] * sb);
        v.z = cvt_tf32(w3[row * GMID + col + 4] * sa);
        v.w = cvt_tf32(w3[(row + 8) * GMID + col + 4] * sb);
        g_w3f[i2] = v;
    }
}

// ---------------------------------------------------------------------------
// K1: grouped 1x1 conv + BN + ReLU -> g_y1 (fp32 scalar, R4 version)
// ---------------------------------------------------------------------------
__global__ __launch_bounds__(256) void k1_conv1(
    const float* __restrict__ x, const float* __restrict__ w1,
    const float* __restrict__ scale1, const float* __restrict__ shift1)
{
    const int tile = blockIdx.x, g = blockIdx.y, n = blockIdx.z;
    const int tid = threadIdx.x, lane = tid & 31, warp = tid >> 5;
    const int wm4 = warp & 3;
    const int wp  = warp >> 2;

    __shared__ float xs[GIN][64];
    __shared__ float wt2[GIN][48];

    const float4* x4 = reinterpret_cast<const float4*>(
        x + ((size_t)n * CIN + g * GIN) * HW + tile * 64);
    for (int i = tid; i < GIN * 16; i += 256) {
        int c = i >> 4, q = i & 15;
        reinterpret_cast<float4*>(xs[c])[q] = x4[c * (HW / 4) + q];
    }
    for (int i = tid; i < GIN * GMID; i += 256) {
        int k = i % GIN, mi = i / GIN;
        wt2[k][(mi / 10) * 12 + (mi % 10)] = w1[(g * GMID + mi) * GIN + k];
    }
    __syncthreads();

    float acc[10] = {};
    #pragma unroll 2
    for (int k = 0; k < GIN; k++) {
        float b = xs[k][wp * 32 + lane];
        const float* wr = &wt2[k][wm4 * 12];
        float4 wa = *reinterpret_cast<const float4*>(wr);
        float4 wb = *reinterpret_cast<const float4*>(wr + 4);
        float2 wc = *reinterpret_cast<const float2*>(wr + 8);
        acc[0] = fmaf(wa.x, b, acc[0]); acc[1] = fmaf(wa.y, b, acc[1]);
        acc[2] = fmaf(wa.z, b, acc[2]); acc[3] = fmaf(wa.w, b, acc[3]);
        acc[4] = fmaf(wb.x, b, acc[4]); acc[5] = fmaf(wb.y, b, acc[5]);
        acc[6] = fmaf(wb.z, b, acc[6]); acc[7] = fmaf(wb.w, b, acc[7]);
        acc[8] = fmaf(wc.x, b, acc[8]); acc[9] = fmaf(wc.y, b, acc[9]);
    }

    float* yp = g_y1 + (size_t)n * MID * HW + tile * 64 + wp * 32 + lane;
    #pragma unroll
    for (int j = 0; j < 10; j++) {
        int mg = g * GMID + wm4 * 10 + j;
        yp[(size_t)mg * HW] = fmaxf(fmaf(acc[j], scale1[mg], shift1[mg]), 0.f);
    }
}

// ---------------------------------------------------------------------------
// K2: depthwise 3x3 (pad 1) + BN, channel-shuffled write -> g_y2
// 4 outputs per thread along w (float4 I/O).
// ---------------------------------------------------------------------------
__global__ __launch_bounds__(256) void k2_dw(
    const float* __restrict__ w2, const float* __restrict__ scale2,
    const float* __restrict__ shift2)
{
    int idx = blockIdx.x * 256 + threadIdx.x;   // NB*MID*784 threads exactly
    int q  = idx % 784;
    int nm = idx / 784;
    int m  = nm % MID, n = nm / MID;
    int w0 = (q * 4) % WW, h = (q * 4) / WW;

    const float* p = g_y1 + (size_t)nm * HW + h * WW + w0;
    float l[3][6];
    #pragma unroll
    for (int r = 0; r < 3; r++) {
        int hh = h - 1 + r;
        if (hh >= 0 && hh < HH) {
            const float* pr = p + (r - 1) * WW;
            float4 c4 = *reinterpret_cast<const float4*>(pr);
            l[r][1] = c4.x; l[r][2] = c4.y; l[r][3] = c4.z; l[r][4] = c4.w;
            l[r][0] = (w0 > 0)       ? pr[-1] : 0.f;
            l[r][5] = (w0 + 4 < WW)  ? pr[4]  : 0.f;
        } else {
            #pragma unroll
            for (int j = 0; j < 6; j++) l[r][j] = 0.f;
        }
    }

    const float* wp = w2 + m * 9;
    float wgt[9];
    #pragma unroll
    for (int i = 0; i < 9; i++) wgt[i] = wp[i];

    float s = scale2[m], sh = shift2[m];
    float4 o;
    float* oj = &o.x;
    #pragma unroll
    for (int j = 0; j < 4; j++) {
        float a = 0.f;
        #pragma unroll
        for (int r = 0; r < 3; r++)
            #pragma unroll
            for (int d = 0; d < 3; d++)
                a = fmaf(wgt[r * 3 + d], l[r][j + d], a);
        oj[j] = fmaf(a, s, sh);
    }

    int sc = (m % GMID) * GRP + m / GMID;       // channel shuffle
    *reinterpret_cast<float4*>(g_y2 + ((size_t)n * MID + sc) * HW + h * WW + w0) = o;
}

// ---------------------------------------------------------------------------
// K3: tf32 MMA (R4 structure: 256 thr, warp grid 2m x 4n, 40 acc regs,
// 2 CTAs/SM) + raw-fp32 B path: B tile cp.async'd in natural row-major
// (stride 72 words -> conflict-free fragment LDS), no cvt / no STS staging.
// grid (49, 3, 32). dyn smem = 74240 B.
// ---------------------------------------------------------------------------
#define AW_ELEMS 1600
#define BROW 72                                     // words per B row (288 B)
#define BWORDS (GMID * BROW)                        // 2880
#define SMEM_K3 (2 * AW_ELEMS * 16 + 2 * BWORDS * 4)   // 51200 + 23040 = 74240

static __device__ __forceinline__ void cp_A(uint4* __restrict__ dst,
                                            const uint4* __restrict__ src, int tid)
{
    unsigned d = smem_u32(dst);
    #pragma unroll 2
    for (int i = tid; i < AW_ELEMS; i += 256)
        CP16(d + i * 16, src + i);
}

// B tile: 40 rows x 64 floats (16 x 16B granules per row), row stride 288 B
static __device__ __forceinline__ void cp_B(unsigned* __restrict__ dst,
                                            const float* __restrict__ src, int tid)
{
    unsigned d = smem_u32(dst);
    #pragma unroll
    for (int i = tid; i < 640; i += 256) {
        int row = i >> 4, c4 = i & 15;
        CP16(d + row * (BROW * 4) + c4 * 16, src + (size_t)row * HW + c4 * 4);
    }
}

static __device__ __forceinline__ void compute_chunk(
    const uint4* __restrict__ aw, const unsigned* __restrict__ sB,
    int wm, int wn, int lane, float acc[5][2][4])
{
    const int gid = lane >> 2, tig = lane & 3;
    #pragma unroll
    for (int kq = 0; kq < 5; kq++) {
        unsigned a[5][4];
        #pragma unroll
        for (int j = 0; j < 5; j++)
            *reinterpret_cast<uint4*>(a[j]) = aw[(kq * 10 + wm * 5 + j) * 32 + lane];
        unsigned b[2][2];
        const int kb = kq * 8 + tig;
        #pragma unroll
        for (int t = 0; t < 2; t++) {
            int col = wn * 16 + t * 8 + gid;
            b[t][0] = sB[kb * BROW + col];           // raw fp32 bits as tf32
            b[t][1] = sB[(kb + 4) * BROW + col];
        }
        #pragma unroll
        for (int j = 0; j < 5; j++)
            #pragma unroll
            for (int t = 0; t < 2; t++)
                mma_tf32(acc[j][t], a[j], b[t]);
    }
}

__global__ __launch_bounds__(256, 2) void k3_fused(
    const float* __restrict__ x,
    const float* __restrict__ shift3, const float* __restrict__ shift_sc,
    float* __restrict__ out)
{
    const int tile = blockIdx.x, ct = blockIdx.y, n = blockIdx.z;
    const int tid = threadIdx.x, lane = tid & 31, warp = tid >> 5;
    const int wm = warp & 1;           // m half (80 rows)
    const int wn = warp >> 1;          // 16-px strip
    const int gid = lane >> 2, tig = lane & 3;

    extern __shared__ __align__(16) char smem[];
    uint4*    s_aw = reinterpret_cast<uint4*>(smem);                        // [2][1600]
    unsigned* s_B  = reinterpret_cast<unsigned*>(smem + 2 * AW_ELEMS * 16); // [2][BWORDS]

    float acc[5][2][4];
    #pragma unroll
    for (int j = 0; j < 5; j++)
        #pragma unroll
        for (int t = 0; t < 2; t++)
            #pragma unroll
            for (int c = 0; c < 4; c++) acc[j][t][c] = 0.f;

    // chunk sources: 0 = conv3 (A=g_w3f, B=g_y2), 1..6 = shortcut kc=c-1
    const uint4* a_src[7];
    const float* b_src[7];
    a_src[0] = g_w3f + (size_t)ct * 1600;
    b_src[0] = g_y2 + ((size_t)n * MID + ct * GMID) * HW + tile * 64;
    #pragma unroll
    for (int kc = 0; kc < 6; kc++) {
        a_src[1 + kc] = g_wscf + (size_t)(ct * 6 + kc) * 1600;
        b_src[1 + kc] = x + ((size_t)n * CIN + kc * 40) * HW + tile * 64;
    }

    // prologue: stage chunk 0
    cp_A(s_aw, a_src[0], tid);
    cp_B(s_B, b_src[0], tid);
    CP_COMMIT();

    #pragma unroll 1
    for (int c = 0; c < 7; c++) {
        int cb = c & 1;
        CP_WAIT0();
        __syncthreads();
        if (c < 6) {
            cp_A(s_aw + ((c + 1) & 1) * AW_ELEMS, a_src[c + 1], tid);
            cp_B(s_B + ((c + 1) & 1) * BWORDS, b_src[c + 1], tid);
            CP_COMMIT();
        }
        compute_chunk(s_aw + cb * AW_ELEMS, s_B + cb * BWORDS, wm, wn, lane, acc);
        if (c == 0) {
            // acc := relu(acc + shift3) + shift_sc ; shortcut accumulates on top
            #pragma unroll
            for (int j = 0; j < 5; j++) {
                int rb = ct * GOUT + wm * 80 + j * 16;
                int r0 = rb + gid, r1 = r0 + 8;
                float h3a = shift3[r0], hsa = shift_sc[r0];
                float h3b = shift3[r1], hsb = shift_sc[r1];
                #pragma unroll
                for (int t = 0; t < 2; t++) {
                    acc[j][t][0] = fmaxf(acc[j][t][0] + h3a, 0.f) + hsa;
                    acc[j][t][1] = fmaxf(acc[j][t][1] + h3a, 0.f) + hsa;
                    acc[j][t][2] = fmaxf(acc[j][t][2] + h3b, 0.f) + hsb;
                    acc[j][t][3] = fmaxf(acc[j][t][3] + h3b, 0.f) + hsb;
                }
            }
        }
        __syncthreads();
    }

    // epilogue
    #pragma unroll
    for (int j = 0; j < 5; j++) {
        int rb = ct * GOUT + wm * 80 + j * 16;
        int r0 = rb + gid, r1 = r0 + 8;
        #pragma unroll
        for (int t = 0; t < 2; t++) {
            int px = tile * 64 + wn * 16 + t * 8 + 2 * tig;
            float2 v0, v1;
            v0.x = acc[j][t][0]; v0.y = acc[j][t][1];
            v1.x = acc[j][t][2]; v1.y = acc[j][t][3];
            *reinterpret_cast<float2*>(out + ((size_t)n * COUT + r0) * HW + px) = v0;
            *reinterpret_cast<float2*>(out + ((size_t)n * COUT + r1) * HW + px) = v1;
        }
    }
}

// ---------------------------------------------------------------------------
extern "C" void kernel_launch(void* const* d_in, const int* in_sizes, int n_in,
                              void* d_out, int out_size)
{
    const float* x        = (const float*)d_in[0];
    const float* w1       = (const float*)d_in[1];
    const float* scale1   = (const float*)d_in[2];
    const float* shift1   = (const float*)d_in[3];
    const float* w2       = (const float*)d_in[4];
    const float* scale2   = (const float*)d_in[5];
    const float* shift2   = (const float*)d_in[6];
    const float* w3       = (const float*)d_in[7];
    const float* scale3   = (const float*)d_in[8];
    const float* shift3   = (const float*)d_in[9];
    const float* wsc      = (const float*)d_in[10];
    const float* scale_sc = (const float*)d_in[11];
    const float* shift_sc = (const float*)d_in[12];
    float* out = (float*)d_out;

    cudaFuncSetAttribute(k3_fused, cudaFuncAttributeMaxDynamicSharedMemorySize, SMEM_K3);

    prep_w<<<(28800 + 4800 + 255) / 256, 256>>>(wsc, w3, scale_sc, scale3);
    k1_conv1<<<dim3(49, 3, 32), 256>>>(x, w1, scale1, shift1);
    k2_dw<<<dim3((NB * MID * 784) / 256), 256>>>(w2, scale2, shift2);
    k3_fused<<<dim3(49, 3, 32), 256, SMEM_K3>>>(x, shift3, shift_sc, out);
}

// round 7
// speedup vs baseline: 1.4998x; 1.1702x over previous
#include <cuda_runtime.h>
#include <cuda_fp16.h>

#define NB   32
#define CIN  240
#define HH   56
#define WW   56
#define HW   3136
#define MID  120
#define COUT 480
#define GRP  3
#define GIN  80    // Cin / G
#define GMID 40    // mid / G
#define GOUT 160   // Cout / G

// Scratch (allocation-free rule: __device__ globals)
__device__ float    g_y1[NB * MID * HW];        // conv1 output (post BN+ReLU), fp32
__device__ unsigned g_xh[NB * 120 * HW];        // x as k-pair-packed half2 words [n][kk<120][px]
__device__ unsigned g_y2h[NB * 72 * HW];        // dw out, SHUFFLED, packed half2, 24 kk-rows/group (20 used + 4 zero)
// Pre-packed fp16 A-fragments (mma.m16n8k16 per-lane layout), BN scale FOLDED IN
// wsc*scale_sc: [ct3][kc5][kt3][mt10][lane32] -> 14400 uint4
// w3 *scale3  : [ct3][kt3][mt10][lane32]      -> 2880 uint4 (K padded 40->48 w/ zeros)
__device__ uint4 g_wscf[14400];
__device__ uint4 g_w3f[2880];

static __device__ __forceinline__ unsigned pack_h2(float lo, float hi) {
    __half2 h = __floats2half2_rn(lo, hi);
    return *reinterpret_cast<unsigned*>(&h);
}

static __device__ __forceinline__ void mma_f16(float c[4], const unsigned a[4],
                                               const unsigned b[2]) {
    asm volatile(
        "mma.sync.aligned.m16n8k16.row.col.f32.f16.f16.f32 "
        "{%0,%1,%2,%3}, {%4,%5,%6,%7}, {%8,%9}, {%0,%1,%2,%3};"
        : "+f"(c[0]), "+f"(c[1]), "+f"(c[2]), "+f"(c[3])
        : "r"(a[0]), "r"(a[1]), "r"(a[2]), "r"(a[3]), "r"(b[0]), "r"(b[1]));
}

static __device__ __forceinline__ unsigned smem_u32(const void* p) {
    return (unsigned)__cvta_generic_to_shared(p);
}
#define CP16(dst, src) \
    asm volatile("cp.async.cg.shared.global [%0], [%1], 16;" :: "r"(dst), "l"(src))
#define CP_COMMIT() asm volatile("cp.async.commit_group;")
#define CP_WAIT0()  asm volatile("cp.async.wait_group 0;")

// ---------------------------------------------------------------------------
// prep_w: pack wsc/w3 into per-lane fp16 m16n8k16 A-fragments, scales folded.
// a0=(row,c0|c1) a1=(row+8,c0|c1) a2=(row,c2|c3) a3=(row+8,c2|c3); lo=even k.
// ---------------------------------------------------------------------------
__global__ void prep_w(const float* __restrict__ wsc, const float* __restrict__ w3,
                       const float* __restrict__ scale_sc, const float* __restrict__ scale3)
{
    int idx = blockIdx.x * 256 + threadIdx.x;
    if (idx < 14400) {
        int lane = idx & 31; int r = idx >> 5;
        int mt = r % 10; r /= 10;
        int kt = r % 3;  r /= 3;
        int kc = r % 5;  int ct = r / 5;
        int gid = lane >> 2, tig = lane & 3;
        int row = ct * GOUT + mt * 16 + gid;
        int c0 = kc * 48 + kt * 16 + 2 * tig;
        int c2 = c0 + 8;
        float sa = scale_sc[row], sb = scale_sc[row + 8];
        const float* wr0 = wsc + (size_t)row * CIN;
        const float* wr8 = wsc + (size_t)(row + 8) * CIN;
        uint4 v;
        v.x = pack_h2(wr0[c0] * sa, wr0[c0 + 1] * sa);
        v.y = pack_h2(wr8[c0] * sb, wr8[c0 + 1] * sb);
        v.z = pack_h2(wr0[c2] * sa, wr0[c2 + 1] * sa);
        v.w = pack_h2(wr8[c2] * sb, wr8[c2 + 1] * sb);
        g_wscf[idx] = v;
    } else if (idx < 14400 + 2880) {
        int i2 = idx - 14400;
        int lane = i2 & 31; int r = i2 >> 5;
        int mt = r % 10; r /= 10;
        int kt = r % 3;  int ct = r / 3;
        int gid = lane >> 2, tig = lane & 3;
        int row = ct * GOUT + mt * 16 + gid;
        int c0 = kt * 16 + 2 * tig;
        int c2 = c0 + 8;
        float sa = scale3[row], sb = scale3[row + 8];
        const float* wr0 = w3 + (size_t)row * GMID;
        const float* wr8 = w3 + (size_t)(row + 8) * GMID;
        float e00 = (c0     < GMID) ? wr0[c0]     : 0.f;
        float e01 = (c0 + 1 < GMID) ? wr0[c0 + 1] : 0.f;
        float e80 = (c0     < GMID) ? wr8[c0]     : 0.f;
        float e81 = (c0 + 1 < GMID) ? wr8[c0 + 1] : 0.f;
        float f00 = (c2     < GMID) ? wr0[c2]     : 0.f;
        float f01 = (c2 + 1 < GMID) ? wr0[c2 + 1] : 0.f;
        float f80 = (c2     < GMID) ? wr8[c2]     : 0.f;
        float f81 = (c2 + 1 < GMID) ? wr8[c2 + 1] : 0.f;
        uint4 v;
        v.x = pack_h2(e00 * sa, e01 * sa);
        v.y = pack_h2(e80 * sb, e81 * sb);
        v.z = pack_h2(f00 * sa, f01 * sa);
        v.w = pack_h2(f80 * sb, f81 * sb);
        g_w3f[i2] = v;
    }
}

// ---------------------------------------------------------------------------
// prep_x: convert x to fp16, packing adjacent k-pairs into half2 words.
// g_xh[n][kk][px] = half2(x[n][2kk][px], x[n][2kk+1][px])
// ---------------------------------------------------------------------------
__global__ __launch_bounds__(256) void prep_x(const float* __restrict__ x)
{
    int idx = blockIdx.x * 256 + threadIdx.x;    // NB*120*784 exactly
    int q  = idx % 784;
    int r  = idx / 784;
    int kk = r % 120, n = r / 120;
    const float4* r0 = reinterpret_cast<const float4*>(x) + ((size_t)n * CIN + 2 * kk) * 784 + q;
    const float4* r1 = r0 + 784;
    float4 a = *r0, b = *r1;
    uint4 o;
    o.x = pack_h2(a.x, b.x);
    o.y = pack_h2(a.y, b.y);
    o.z = pack_h2(a.z, b.z);
    o.w = pack_h2(a.w, b.w);
    reinterpret_cast<uint4*>(g_xh)[((size_t)n * 120 + kk) * 784 + q] = o;
}

// ---------------------------------------------------------------------------
// zero_pad: zero the 4 padded kk-rows per group in g_y2h (k 40..47 of conv3).
// ---------------------------------------------------------------------------
__global__ __launch_bounds__(256) void zero_pad()
{
    int idx = blockIdx.x * 256 + threadIdx.x;    // NB*12*784 exactly
    int q = idx % 784;
    int r = (idx / 784) % 12;
    int n = idx / (784 * 12);
    int kk = (r >> 2) * 24 + 20 + (r & 3);
    reinterpret_cast<uint4*>(g_y2h)[((size_t)n * 72 + kk) * 784 + q] = make_uint4(0, 0, 0, 0);
}

// ---------------------------------------------------------------------------
// K1: grouped 1x1 conv + BN + ReLU -> g_y1 (fp32 scalar, unchanged)
// ---------------------------------------------------------------------------
__global__ __launch_bounds__(256) void k1_conv1(
    const float* __restrict__ x, const float* __restrict__ w1,
    const float* __restrict__ scale1, const float* __restrict__ shift1)
{
    const int tile = blockIdx.x, g = blockIdx.y, n = blockIdx.z;
    const int tid = threadIdx.x, lane = tid & 31, warp = tid >> 5;
    const int wm4 = warp & 3;
    const int wp  = warp >> 2;

    __shared__ float xs[GIN][64];
    __shared__ float wt2[GIN][48];

    const float4* x4 = reinterpret_cast<const float4*>(
        x + ((size_t)n * CIN + g * GIN) * HW + tile * 64);
    for (int i = tid; i < GIN * 16; i += 256) {
        int c = i >> 4, q = i & 15;
        reinterpret_cast<float4*>(xs[c])[q] = x4[c * (HW / 4) + q];
    }
    for (int i = tid; i < GIN * GMID; i += 256) {
        int k = i % GIN, mi = i / GIN;
        wt2[k][(mi / 10) * 12 + (mi % 10)] = w1[(g * GMID + mi) * GIN + k];
    }
    __syncthreads();

    float acc[10] = {};
    #pragma unroll 2
    for (int k = 0; k < GIN; k++) {
        float b = xs[k][wp * 32 + lane];
        const float* wr = &wt2[k][wm4 * 12];
        float4 wa = *reinterpret_cast<const float4*>(wr);
        float4 wb = *reinterpret_cast<const float4*>(wr + 4);
        float2 wc = *reinterpret_cast<const float2*>(wr + 8);
        acc[0] = fmaf(wa.x, b, acc[0]); acc[1] = fmaf(wa.y, b, acc[1]);
        acc[2] = fmaf(wa.z, b, acc[2]); acc[3] = fmaf(wa.w, b, acc[3]);
        acc[4] = fmaf(wb.x, b, acc[4]); acc[5] = fmaf(wb.y, b, acc[5]);
        acc[6] = fmaf(wb.z, b, acc[6]); acc[7] = fmaf(wb.w, b, acc[7]);
        acc[8] = fmaf(wc.x, b, acc[8]); acc[9] = fmaf(wc.y, b, acc[9]);
    }

    float* yp = g_y1 + (size_t)n * MID * HW + tile * 64 + wp * 32 + lane;
    #pragma unroll
    for (int j = 0; j < 10; j++) {
        int mg = g * GMID + wm4 * 10 + j;
        yp[(size_t)mg * HW] = fmaxf(fmaf(acc[j], scale1[mg], shift1[mg]), 0.f);
    }
}

// ---------------------------------------------------------------------------
// K2: depthwise 3x3 (pad 1) + BN; computes TWO shuffled channels per thread
// and writes packed half2 words into g_y2h (shuffled pair layout).
// shuffle: s = (m%40)*3 + m/40  <=>  m(s) = (s%3)*40 + s/3
// ---------------------------------------------------------------------------
__global__ __launch_bounds__(256) void k2_dw(
    const float* __restrict__ w2, const float* __restrict__ scale2,
    const float* __restrict__ shift2)
{
    int idx = blockIdx.x * 256 + threadIdx.x;   // NB*60*784 threads exactly
    int q  = idx % 784;
    int r  = idx / 784;
    int kk = r % 60, n = r / 60;
    int s0 = 2 * kk, s1 = 2 * kk + 1;
    int m0 = (s0 % 3) * 40 + s0 / 3;
    int m1 = (s1 % 3) * 40 + s1 / 3;
    int w0 = (q * 4) % WW, h = (q * 4) / WW;

    float v[2][4];
    #pragma unroll
    for (int ch = 0; ch < 2; ch++) {
        int m = ch ? m1 : m0;
        const float* p = g_y1 + ((size_t)n * MID + m) * HW + h * WW + w0;
        float l[3][6];
        #pragma unroll
        for (int rr = 0; rr < 3; rr++) {
            int hh = h - 1 + rr;
            if (hh >= 0 && hh < HH) {
                const float* pr = p + (rr - 1) * WW;
                float4 c4 = *reinterpret_cast<const float4*>(pr);
                l[rr][1] = c4.x; l[rr][2] = c4.y; l[rr][3] = c4.z; l[rr][4] = c4.w;
                l[rr][0] = (w0 > 0)      ? pr[-1] : 0.f;
                l[rr][5] = (w0 + 4 < WW) ? pr[4]  : 0.f;
            } else {
                #pragma unroll
                for (int j = 0; j < 6; j++) l[rr][j] = 0.f;
            }
        }
        const float* wp = w2 + m * 9;
        float wgt[9];
        #pragma unroll
        for (int i = 0; i < 9; i++) wgt[i] = wp[i];
        float sc = scale2[m], sh = shift2[m];
        #pragma unroll
        for (int j = 0; j < 4; j++) {
            float a = 0.f;
            #pragma unroll
            for (int rr = 0; rr < 3; rr++)
                #pragma unroll
                for (int d = 0; d < 3; d++)
                    a = fmaf(wgt[rr * 3 + d], l[rr][j + d], a);
            v[ch][j] = fmaf(a, sc, sh);
        }
    }

    // dest kk-row in padded-group layout: group g24 = s0/40, row = g*24 + (s0%40)/2
    int row = (s0 / 40) * 24 + (s0 % 40) / 2;
    uint4 o;
    o.x = pack_h2(v[0][0], v[1][0]);
    o.y = pack_h2(v[0][1], v[1][1]);
    o.z = pack_h2(v[0][2], v[1][2]);
    o.w = pack_h2(v[0][3], v[1][3]);
    reinterpret_cast<uint4*>(g_y2h)[((size_t)n * 72 + row) * 784 + q] = o;
}

// ---------------------------------------------------------------------------
// K3: fp16 m16n8k16 MMA. 256 thr, warp grid 2m x 4n, K chunks of 48 (3 kt).
// A frags + B half2 tiles both cp.async double-buffered. 2 CTAs/SM.
// chunk 0 = conv3 (padded K48) -> relu transform -> chunks 1..5 shortcut.
// ---------------------------------------------------------------------------
#define AW_ELEMS 960                                 // uint4 per chunk
#define BROW 72                                      // half2 words per kk row (pad 8)
#define BWORDS (24 * BROW)                           // 1728
#define SMEM_K3 (2 * AW_ELEMS * 16 + 2 * BWORDS * 4) // 30720 + 13824 = 44544

static __device__ __forceinline__ void cp_A(uint4* __restrict__ dst,
                                            const uint4* __restrict__ src, int tid)
{
    unsigned d = smem_u32(dst);
    #pragma unroll
    for (int i = tid; i < AW_ELEMS; i += 256)
        CP16(d + i * 16, src + i);
}

// B tile: 24 kk-rows x 64 half2 (16 x 16B granules per row), row stride 288 B
static __device__ __forceinline__ void cp_B(unsigned* __restrict__ dst,
                                            const unsigned* __restrict__ src, int tid)
{
    unsigned d = smem_u32(dst);
    #pragma unroll
    for (int i = tid; i < 384; i += 256) {
        int row = i >> 4, c4 = i & 15;
        CP16(d + row * (BROW * 4) + c4 * 16, src + (size_t)row * HW + c4 * 4);
    }
}

static __device__ __forceinline__ void compute_chunk(
    const uint4* __restrict__ aw, const unsigned* __restrict__ sB,
    int wm, int wn, int lane, float acc[5][2][4])
{
    const int gid = lane >> 2, tig = lane & 3;
    #pragma unroll
    for (int kt = 0; kt < 3; kt++) {
        unsigned a[5][4];
        #pragma unroll
        for (int j = 0; j < 5; j++)
            *reinterpret_cast<uint4*>(a[j]) = aw[(kt * 10 + wm * 5 + j) * 32 + lane];
        unsigned b[2][2];
        const int kb = kt * 8 + tig;
        #pragma unroll
        for (int t = 0; t < 2; t++) {
            int col = wn * 16 + t * 8 + gid;
            b[t][0] = sB[kb * BROW + col];
            b[t][1] = sB[(kb + 4) * BROW + col];
        }
        #pragma unroll
        for (int j = 0; j < 5; j++)
            #pragma unroll
            for (int t = 0; t < 2; t++)
                mma_f16(acc[j][t], a[j], b[t]);
    }
}

__global__ __launch_bounds__(256, 2) void k3_fused(
    const float* __restrict__ shift3, const float* __restrict__ shift_sc,
    float* __restrict__ out)
{
    const int tile = blockIdx.x, ct = blockIdx.y, n = blockIdx.z;
    const int tid = threadIdx.x, lane = tid & 31, warp = tid >> 5;
    const int wm = warp & 1;           // m half (80 rows)
    const int wn = warp >> 1;          // 16-px strip
    const int gid = lane >> 2, tig = lane & 3;

    extern __shared__ __align__(16) char smem[];
    uint4*    s_aw = reinterpret_cast<uint4*>(smem);                        // [2][960]
    unsigned* s_B  = reinterpret_cast<unsigned*>(smem + 2 * AW_ELEMS * 16); // [2][BWORDS]

    float acc[5][2][4];
    #pragma unroll
    for (int j = 0; j < 5; j++)
        #pragma unroll
        for (int t = 0; t < 2; t++)
            #pragma unroll
            for (int c = 0; c < 4; c++) acc[j][t][c] = 0.f;

    // chunk sources: 0 = conv3 (A=g_w3f, B=g_y2h group ct), 1..5 = shortcut
    const uint4* a_src[6];
    const unsigned* b_src[6];
    a_src[0] = g_w3f + (size_t)ct * 960;
    b_src[0] = g_y2h + ((size_t)n * 72 + ct * 24) * HW + tile * 64;
    #pragma unroll
    for (int kc = 0; kc < 5; kc++) {
        a_src[1 + kc] = g_wscf + (size_t)(ct * 5 + kc) * 960;
        b_src[1 + kc] = g_xh + ((size_t)n * 120 + kc * 24) * HW + tile * 64;
    }

    // prologue: stage chunk 0
    cp_A(s_aw, a_src[0], tid);
    cp_B(s_B, b_src[0], tid);
    CP_COMMIT();

    #pragma unroll 1
    for (int c = 0; c < 6; c++) {
        int cb = c & 1;
        CP_WAIT0();
        __syncthreads();
        if (c < 5) {
            cp_A(s_aw + ((c + 1) & 1) * AW_ELEMS, a_src[c + 1], tid);
            cp_B(s_B + ((c + 1) & 1) * BWORDS, b_src[c + 1], tid);
            CP_COMMIT();
        }
        compute_chunk(s_aw + cb * AW_ELEMS, s_B + cb * BWORDS, wm, wn, lane, acc);
        if (c == 0) {
            // acc := relu(acc + shift3) + shift_sc ; shortcut accumulates on top
            #pragma unroll
            for (int j = 0; j < 5; j++) {
                int rb = ct * GOUT + wm * 80 + j * 16;
                int r0 = rb + gid, r1 = r0 + 8;
                float h3a = shift3[r0], hsa = shift_sc[r0];
                float h3b = shift3[r1], hsb = shift_sc[r1];
                #pragma unroll
                for (int t = 0; t < 2; t++) {
                    acc[j][t][0] = fmaxf(acc[j][t][0] + h3a, 0.f) + hsa;
                    acc[j][t][1] = fmaxf(acc[j][t][1] + h3a, 0.f) + hsa;
                    acc[j][t][2] = fmaxf(acc[j][t][2] + h3b, 0.f) + hsb;
                    acc[j][t][3] = fmaxf(acc[j][t][3] + h3b, 0.f) + hsb;
                }
            }
        }
        __syncthreads();
    }

    // epilogue
    #pragma unroll
    for (int j = 0; j < 5; j++) {
        int rb = ct * GOUT + wm * 80 + j * 16;
        int r0 = rb + gid, r1 = r0 + 8;
        #pragma unroll
        for (int t = 0; t < 2; t++) {
            int px = tile * 64 + wn * 16 + t * 8 + 2 * tig;
            float2 v0, v1;
            v0.x = acc[j][t][0]; v0.y = acc[j][t][1];
            v1.x = acc[j][t][2]; v1.y = acc[j][t][3];
            *reinterpret_cast<float2*>(out + ((size_t)n * COUT + r0) * HW + px) = v0;
            *reinterpret_cast<float2*>(out + ((size_t)n * COUT + r1) * HW + px) = v1;
        }
    }
}

// ---------------------------------------------------------------------------
extern "C" void kernel_launch(void* const* d_in, const int* in_sizes, int n_in,
                              void* d_out, int out_size)
{
    const float* x        = (const float*)d_in[0];
    const float* w1       = (const float*)d_in[1];
    const float* scale1   = (const float*)d_in[2];
    const float* shift1   = (const float*)d_in[3];
    const float* w2       = (const float*)d_in[4];
    const float* scale2   = (const float*)d_in[5];
    const float* shift2   = (const float*)d_in[6];
    const float* w3       = (const float*)d_in[7];
    const float* scale3   = (const float*)d_in[8];
    const float* shift3   = (const float*)d_in[9];
    const float* wsc      = (const float*)d_in[10];
    const float* scale_sc = (const float*)d_in[11];
    const float* shift_sc = (const float*)d_in[12];
    float* out = (float*)d_out;

    cudaFuncSetAttribute(k3_fused, cudaFuncAttributeMaxDynamicSharedMemorySize, SMEM_K3);

    prep_w<<<(14400 + 2880 + 255) / 256, 256>>>(wsc, w3, scale_sc, scale3);
    prep_x<<<(NB * 120 * 784) / 256, 256>>>(x);
    zero_pad<<<(NB * 12 * 784) / 256, 256>>>();
    k1_conv1<<<dim3(49, 3, 32), 256>>>(x, w1, scale1, shift1);
    k2_dw<<<(NB * 60 * 784) / 256, 256>>>(w2, scale2, shift2);
    k3_fused<<<dim3(49, 3, 32), 256, SMEM_K3>>>(shift3, shift_sc, out);
}

// round 8
// speedup vs baseline: 2.0810x; 1.3876x over previous
#include <cuda_runtime.h>
#include <cuda_fp16.h>

#define NB   32
#define CIN  240
#define HH   56
#define WW   56
#define HW   3136
#define MID  120
#define COUT 480
#define GRP  3
#define GIN  80    // Cin / G
#define GMID 40    // mid / G
#define GOUT 160   // Cout / G

// Scratch (allocation-free rule: __device__ globals)
__device__ float    g_y1[NB * MID * HW];        // conv1 output (post BN+ReLU), fp32
__device__ unsigned g_xh[NB * 120 * HW];        // x as k-pair-packed half2 words [n][kk<120][px]
__device__ unsigned g_y2h[NB * 72 * HW];        // dw out, SHUFFLED, packed half2, 24 kk-rows/group (20 used + 4 zero)
// Pre-packed fp16 A-fragments (mma.m16n8k16 per-lane layout), BN scale FOLDED IN
__device__ uint4 g_wscf[14400];   // wsc*scale_sc: [ct3][kc5][kt3][mt10][lane32]
__device__ uint4 g_w3f[2880];     // w3*scale3:    [ct3][kt3][mt10][lane32] (K 40->48 zero-pad)
__device__ uint4 g_w1f[1440];     // w1*scale1:    [g3][kt5][mt3][lane32]  (M 40->48 zero-pad)

static __device__ __forceinline__ unsigned pack_h2(float lo, float hi) {
    __half2 h = __floats2half2_rn(lo, hi);
    return *reinterpret_cast<unsigned*>(&h);
}

static __device__ __forceinline__ void mma_f16(float c[4], const unsigned a[4],
                                               const unsigned b[2]) {
    asm volatile(
        "mma.sync.aligned.m16n8k16.row.col.f32.f16.f16.f32 "
        "{%0,%1,%2,%3}, {%4,%5,%6,%7}, {%8,%9}, {%0,%1,%2,%3};"
        : "+f"(c[0]), "+f"(c[1]), "+f"(c[2]), "+f"(c[3])
        : "r"(a[0]), "r"(a[1]), "r"(a[2]), "r"(a[3]), "r"(b[0]), "r"(b[1]));
}

static __device__ __forceinline__ unsigned smem_u32(const void* p) {
    return (unsigned)__cvta_generic_to_shared(p);
}
#define CP16(dst, src) \
    asm volatile("cp.async.cg.shared.global [%0], [%1], 16;" :: "r"(dst), "l"(src))
#define CP_COMMIT() asm volatile("cp.async.commit_group;")
#define CP_WAIT0()  asm volatile("cp.async.wait_group 0;")

// ---------------------------------------------------------------------------
// prep_w: pack wsc/w3/w1 into per-lane fp16 m16n8k16 A-fragments, scales folded.
// ---------------------------------------------------------------------------
__global__ void prep_w(const float* __restrict__ wsc, const float* __restrict__ w3,
                       const float* __restrict__ w1,
                       const float* __restrict__ scale_sc, const float* __restrict__ scale3,
                       const float* __restrict__ scale1)
{
    int idx = blockIdx.x * 256 + threadIdx.x;
    if (idx < 14400) {
        int lane = idx & 31; int r = idx >> 5;
        int mt = r % 10; r /= 10;
        int kt = r % 3;  r /= 3;
        int kc = r % 5;  int ct = r / 5;
        int gid = lane >> 2, tig = lane & 3;
        int row = ct * GOUT + mt * 16 + gid;
        int c0 = kc * 48 + kt * 16 + 2 * tig;
        int c2 = c0 + 8;
        float sa = scale_sc[row], sb = scale_sc[row + 8];
        const float* wr0 = wsc + (size_t)row * CIN;
        const float* wr8 = wsc + (size_t)(row + 8) * CIN;
        uint4 v;
        v.x = pack_h2(wr0[c0] * sa, wr0[c0 + 1] * sa);
        v.y = pack_h2(wr8[c0] * sb, wr8[c0 + 1] * sb);
        v.z = pack_h2(wr0[c2] * sa, wr0[c2 + 1] * sa);
        v.w = pack_h2(wr8[c2] * sb, wr8[c2 + 1] * sb);
        g_wscf[idx] = v;
    } else if (idx < 14400 + 2880) {
        int i2 = idx - 14400;
        int lane = i2 & 31; int r = i2 >> 5;
        int mt = r % 10; r /= 10;
        int kt = r % 3;  int ct = r / 3;
        int gid = lane >> 2, tig = lane & 3;
        int row = ct * GOUT + mt * 16 + gid;
        int c0 = kt * 16 + 2 * tig;
        int c2 = c0 + 8;
        float sa = scale3[row], sb = scale3[row + 8];
        const float* wr0 = w3 + (size_t)row * GMID;
        const float* wr8 = w3 + (size_t)(row + 8) * GMID;
        float e00 = (c0     < GMID) ? wr0[c0]     : 0.f;
        float e01 = (c0 + 1 < GMID) ? wr0[c0 + 1] : 0.f;
        float e80 = (c0     < GMID) ? wr8[c0]     : 0.f;
        float e81 = (c0 + 1 < GMID) ? wr8[c0 + 1] : 0.f;
        float f00 = (c2     < GMID) ? wr0[c2]     : 0.f;
        float f01 = (c2 + 1 < GMID) ? wr0[c2 + 1] : 0.f;
        float f80 = (c2     < GMID) ? wr8[c2]     : 0.f;
        float f81 = (c2 + 1 < GMID) ? wr8[c2 + 1] : 0.f;
        uint4 v;
        v.x = pack_h2(e00 * sa, e01 * sa);
        v.y = pack_h2(e80 * sb, e81 * sb);
        v.z = pack_h2(f00 * sa, f01 * sa);
        v.w = pack_h2(f80 * sb, f81 * sb);
        g_w3f[i2] = v;
    } else if (idx < 14400 + 2880 + 1440) {
        int i3 = idx - 14400 - 2880;
        int lane = i3 & 31; int r = i3 >> 5;
        int mt = r % 3; r /= 3;
        int kt = r % 5; int g = r / 5;
        int gid = lane >> 2, tig = lane & 3;
        int r0 = mt * 16 + gid;          // row within 48-tile; valid if < 40
        int r1 = r0 + 8;
        int c0 = kt * 16 + 2 * tig;
        int c2 = c0 + 8;
        float sa = (r0 < GMID) ? scale1[g * GMID + r0] : 0.f;
        float sb = (r1 < GMID) ? scale1[g * GMID + r1] : 0.f;
        const float* wr0 = w1 + ((size_t)g * GMID + r0) * GIN;
        const float* wr8 = w1 + ((size_t)g * GMID + r1) * GIN;
        float e00 = (r0 < GMID) ? wr0[c0]     : 0.f;
        float e01 = (r0 < GMID) ? wr0[c0 + 1] : 0.f;
        float e80 = (r1 < GMID) ? wr8[c0]     : 0.f;
        float e81 = (r1 < GMID) ? wr8[c0 + 1] : 0.f;
        float f00 = (r0 < GMID) ? wr0[c2]     : 0.f;
        float f01 = (r0 < GMID) ? wr0[c2 + 1] : 0.f;
        float f80 = (r1 < GMID) ? wr8[c2]     : 0.f;
        float f81 = (r1 < GMID) ? wr8[c2 + 1] : 0.f;
        uint4 v;
        v.x = pack_h2(e00 * sa, e01 * sa);
        v.y = pack_h2(e80 * sb, e81 * sb);
        v.z = pack_h2(f00 * sa, f01 * sa);
        v.w = pack_h2(f80 * sb, f81 * sb);
        g_w1f[i3] = v;
    }
}

// ---------------------------------------------------------------------------
// prep_x: convert x to fp16, packing adjacent k-pairs into half2 words.
// ---------------------------------------------------------------------------
__global__ __launch_bounds__(256) void prep_x(const float* __restrict__ x)
{
    int idx = blockIdx.x * 256 + threadIdx.x;    // NB*120*784 exactly
    int q  = idx % 784;
    int r  = idx / 784;
    int kk = r % 120, n = r / 120;
    const float4* r0 = reinterpret_cast<const float4*>(x) + ((size_t)n * CIN + 2 * kk) * 784 + q;
    const float4* r1 = r0 + 784;
    float4 a = *r0, b = *r1;
    uint4 o;
    o.x = pack_h2(a.x, b.x);
    o.y = pack_h2(a.y, b.y);
    o.z = pack_h2(a.z, b.z);
    o.w = pack_h2(a.w, b.w);
    reinterpret_cast<uint4*>(g_xh)[((size_t)n * 120 + kk) * 784 + q] = o;
}

// ---------------------------------------------------------------------------
// zero_pad: zero the 4 padded kk-rows per group in g_y2h.
// ---------------------------------------------------------------------------
__global__ __launch_bounds__(256) void zero_pad()
{
    int idx = blockIdx.x * 256 + threadIdx.x;    // NB*12*784 exactly
    int q = idx % 784;
    int r = (idx / 784) % 12;
    int n = idx / (784 * 12);
    int kk = (r >> 2) * 24 + 20 + (r & 3);
    reinterpret_cast<uint4*>(g_y2h)[((size_t)n * 72 + kk) * 784 + q] = make_uint4(0, 0, 0, 0);
}

// ---------------------------------------------------------------------------
// K1 (MMA): grouped 1x1 conv + BN(+scale folded) + ReLU -> g_y1 (fp32)
// M=48 (40 valid), K=80 (5 kt), N=64 px. grid (49, 3, 32), 128 thr.
// Warp wn owns 16-px strip x all 3 m-tiles. B = g_xh kk rows [40g, 40g+40).
// ---------------------------------------------------------------------------
#define BROW1 72
__global__ __launch_bounds__(128) void k1_mma(
    const float* __restrict__ shift1)
{
    const int tile = blockIdx.x, g = blockIdx.y, n = blockIdx.z;
    const int tid = threadIdx.x, lane = tid & 31, wn = tid >> 5;
    const int gid = lane >> 2, tig = lane & 3;

    __shared__ __align__(16) uint4    s_a[480];          // 5kt x 3mt x 32
    __shared__ __align__(16) unsigned s_B[40 * BROW1];   // 40 kk-rows x 64 (+8 pad)

    // stage A fragments
    {
        unsigned d = smem_u32(s_a);
        const uint4* src = g_w1f + (size_t)g * 480;
        #pragma unroll
        for (int i = tid; i < 480; i += 128)
            CP16(d + i * 16, src + i);
    }
    // stage B: g_xh rows [40g .. 40g+40)
    {
        unsigned d = smem_u32(s_B);
        const unsigned* src = g_xh + ((size_t)n * 120 + g * 40) * HW + tile * 64;
        #pragma unroll
        for (int i = tid; i < 640; i += 128) {
            int row = i >> 4, c4 = i & 15;
            CP16(d + row * (BROW1 * 4) + c4 * 16, src + (size_t)row * HW + c4 * 4);
        }
    }
    CP_COMMIT();
    CP_WAIT0();
    __syncthreads();

    float acc[3][2][4];
    #pragma unroll
    for (int mt = 0; mt < 3; mt++)
        #pragma unroll
        for (int t = 0; t < 2; t++)
            #pragma unroll
            for (int c = 0; c < 4; c++) acc[mt][t][c] = 0.f;

    #pragma unroll
    for (int kt = 0; kt < 5; kt++) {
        unsigned a[3][4];
        #pragma unroll
        for (int mt = 0; mt < 3; mt++)
            *reinterpret_cast<uint4*>(a[mt]) = s_a[(kt * 3 + mt) * 32 + lane];
        unsigned b[2][2];
        const int kb = kt * 8 + tig;
        #pragma unroll
        for (int t = 0; t < 2; t++) {
            int col = wn * 16 + t * 8 + gid;
            b[t][0] = s_B[kb * BROW1 + col];
            b[t][1] = s_B[(kb + 4) * BROW1 + col];
        }
        #pragma unroll
        for (int mt = 0; mt < 3; mt++)
            #pragma unroll
            for (int t = 0; t < 2; t++)
                mma_f16(acc[mt][t], a[mt], b[t]);
    }

    // epilogue: relu(acc + shift1) -> fp32 g_y1 (rows >= 40 discarded)
    #pragma unroll
    for (int mt = 0; mt < 3; mt++) {
        int r0 = mt * 16 + gid;        // < 40 always (mt=2: 32+gid<=39)
        int r1 = r0 + 8;               // invalid when mt==2
        int m0 = g * GMID + r0;
        float h0 = shift1[m0];
        float h1 = (r1 < GMID) ? shift1[g * GMID + r1] : 0.f;
        #pragma unroll
        for (int t = 0; t < 2; t++) {
            int px = tile * 64 + wn * 16 + t * 8 + 2 * tig;
            float2 v0, v1;
            v0.x = fmaxf(acc[mt][t][0] + h0, 0.f);
            v0.y = fmaxf(acc[mt][t][1] + h0, 0.f);
            *reinterpret_cast<float2*>(g_y1 + ((size_t)n * MID + m0) * HW + px) = v0;
            if (r1 < GMID) {
                v1.x = fmaxf(acc[mt][t][2] + h1, 0.f);
                v1.y = fmaxf(acc[mt][t][3] + h1, 0.f);
                *reinterpret_cast<float2*>(g_y1 + ((size_t)n * MID + g * GMID + r1) * HW + px) = v1;
            }
        }
    }
}

// ---------------------------------------------------------------------------
// K2: depthwise 3x3 (pad 1) + BN; two shuffled channels per thread,
// packed half2 write into g_y2h.
// ---------------------------------------------------------------------------
__global__ __launch_bounds__(256) void k2_dw(
    const float* __restrict__ w2, const float* __restrict__ scale2,
    const float* __restrict__ shift2)
{
    int idx = blockIdx.x * 256 + threadIdx.x;   // NB*60*784 threads exactly
    int q  = idx % 784;
    int r  = idx / 784;
    int kk = r % 60, n = r / 60;
    int s0 = 2 * kk, s1 = 2 * kk + 1;
    int m0 = (s0 % 3) * 40 + s0 / 3;
    int m1 = (s1 % 3) * 40 + s1 / 3;
    int w0 = (q * 4) % WW, h = (q * 4) / WW;

    float v[2][4];
    #pragma unroll
    for (int ch = 0; ch < 2; ch++) {
        int m = ch ? m1 : m0;
        const float* p = g_y1 + ((size_t)n * MID + m) * HW + h * WW + w0;
        float l[3][6];
        #pragma unroll
        for (int rr = 0; rr < 3; rr++) {
            int hh = h - 1 + rr;
            if (hh >= 0 && hh < HH) {
                const float* pr = p + (rr - 1) * WW;
                float4 c4 = *reinterpret_cast<const float4*>(pr);
                l[rr][1] = c4.x; l[rr][2] = c4.y; l[rr][3] = c4.z; l[rr][4] = c4.w;
                l[rr][0] = (w0 > 0)      ? pr[-1] : 0.f;
                l[rr][5] = (w0 + 4 < WW) ? pr[4]  : 0.f;
            } else {
                #pragma unroll
                for (int j = 0; j < 6; j++) l[rr][j] = 0.f;
            }
        }
        const float* wp = w2 + m * 9;
        float wgt[9];
        #pragma unroll
        for (int i = 0; i < 9; i++) wgt[i] = wp[i];
        float sc = scale2[m], sh = shift2[m];
        #pragma unroll
        for (int j = 0; j < 4; j++) {
            float a = 0.f;
            #pragma unroll
            for (int rr = 0; rr < 3; rr++)
                #pragma unroll
                for (int d = 0; d < 3; d++)
                    a = fmaf(wgt[rr * 3 + d], l[rr][j + d], a);
            v[ch][j] = fmaf(a, sc, sh);
        }
    }

    int row = (s0 / 40) * 24 + (s0 % 40) / 2;
    uint4 o;
    o.x = pack_h2(v[0][0], v[1][0]);
    o.y = pack_h2(v[0][1], v[1][1]);
    o.z = pack_h2(v[0][2], v[1][2]);
    o.w = pack_h2(v[0][3], v[1][3]);
    reinterpret_cast<uint4*>(g_y2h)[((size_t)n * 72 + row) * 784 + q] = o;
}

// ---------------------------------------------------------------------------
// K3: fp16 m16n8k16 MMA. 256 thr, warp grid 2m x 4n, K chunks of 48 (3 kt).
// ---------------------------------------------------------------------------
#define AW_ELEMS 960
#define BROW 72
#define BWORDS (24 * BROW)
#define SMEM_K3 (2 * AW_ELEMS * 16 + 2 * BWORDS * 4)

static __device__ __forceinline__ void cp_A(uint4* __restrict__ dst,
                                            const uint4* __restrict__ src, int tid)
{
    unsigned d = smem_u32(dst);
    #pragma unroll
    for (int i = tid; i < AW_ELEMS; i += 256)
        CP16(d + i * 16, src + i);
}

static __device__ __forceinline__ void cp_B(unsigned* __restrict__ dst,
                                            const unsigned* __restrict__ src, int tid)
{
    unsigned d = smem_u32(dst);
    #pragma unroll
    for (int i = tid; i < 384; i += 256) {
        int row = i >> 4, c4 = i & 15;
        CP16(d + row * (BROW * 4) + c4 * 16, src + (size_t)row * HW + c4 * 4);
    }
}

static __device__ __forceinline__ void compute_chunk(
    const uint4* __restrict__ aw, const unsigned* __restrict__ sB,
    int wm, int wn, int lane, float acc[5][2][4])
{
    const int gid = lane >> 2, tig = lane & 3;
    #pragma unroll
    for (int kt = 0; kt < 3; kt++) {
        unsigned a[5][4];
        #pragma unroll
        for (int j = 0; j < 5; j++)
            *reinterpret_cast<uint4*>(a[j]) = aw[(kt * 10 + wm * 5 + j) * 32 + lane];
        unsigned b[2][2];
        const int kb = kt * 8 + tig;
        #pragma unroll
        for (int t = 0; t < 2; t++) {
            int col = wn * 16 + t * 8 + gid;
            b[t][0] = sB[kb * BROW + col];
            b[t][1] = sB[(kb + 4) * BROW + col];
        }
        #pragma unroll
        for (int j = 0; j < 5; j++)
            #pragma unroll
            for (int t = 0; t < 2; t++)
                mma_f16(acc[j][t], a[j], b[t]);
    }
}

__global__ __launch_bounds__(256, 2) void k3_fused(
    const float* __restrict__ shift3, const float* __restrict__ shift_sc,
    float* __restrict__ out)
{
    const int tile = blockIdx.x, ct = blockIdx.y, n = blockIdx.z;
    const int tid = threadIdx.x, lane = tid & 31, warp = tid >> 5;
    const int wm = warp & 1;
    const int wn = warp >> 1;
    const int gid = lane >> 2, tig = lane & 3;

    extern __shared__ __align__(16) char smem[];
    uint4*    s_aw = reinterpret_cast<uint4*>(smem);
    unsigned* s_B  = reinterpret_cast<unsigned*>(smem + 2 * AW_ELEMS * 16);

    float acc[5][2][4];
    #pragma unroll
    for (int j = 0; j < 5; j++)
        #pragma unroll
        for (int t = 0; t < 2; t++)
            #pragma unroll
            for (int c = 0; c < 4; c++) acc[j][t][c] = 0.f;

    const uint4* a_src[6];
    const unsigned* b_src[6];
    a_src[0] = g_w3f + (size_t)ct * 960;
    b_src[0] = g_y2h + ((size_t)n * 72 + ct * 24) * HW + tile * 64;
    #pragma unroll
    for (int kc = 0; kc < 5; kc++) {
        a_src[1 + kc] = g_wscf + (size_t)(ct * 5 + kc) * 960;
        b_src[1 + kc] = g_xh + ((size_t)n * 120 + kc * 24) * HW + tile * 64;
    }

    cp_A(s_aw, a_src[0], tid);
    cp_B(s_B, b_src[0], tid);
    CP_COMMIT();

    #pragma unroll 1
    for (int c = 0; c < 6; c++) {
        int cb = c & 1;
        CP_WAIT0();
        __syncthreads();
        if (c < 5) {
            cp_A(s_aw + ((c + 1) & 1) * AW_ELEMS, a_src[c + 1], tid);
            cp_B(s_B + ((c + 1) & 1) * BWORDS, b_src[c + 1], tid);
            CP_COMMIT();
        }
        compute_chunk(s_aw + cb * AW_ELEMS, s_B + cb * BWORDS, wm, wn, lane, acc);
        if (c == 0) {
            #pragma unroll
            for (int j = 0; j < 5; j++) {
                int rb = ct * GOUT + wm * 80 + j * 16;
                int r0 = rb + gid, r1 = r0 + 8;
                float h3a = shift3[r0], hsa = shift_sc[r0];
                float h3b = shift3[r1], hsb = shift_sc[r1];
                #pragma unroll
                for (int t = 0; t < 2; t++) {
                    acc[j][t][0] = fmaxf(acc[j][t][0] + h3a, 0.f) + hsa;
                    acc[j][t][1] = fmaxf(acc[j][t][1] + h3a, 0.f) + hsa;
                    acc[j][t][2] = fmaxf(acc[j][t][2] + h3b, 0.f) + hsb;
                    acc[j][t][3] = fmaxf(acc[j][t][3] + h3b, 0.f) + hsb;
                }
            }
        }
        __syncthreads();
    }

    #pragma unroll
    for (int j = 0; j < 5; j++) {
        int rb = ct * GOUT + wm * 80 + j * 16;
        int r0 = rb + gid, r1 = r0 + 8;
        #pragma unroll
        for (int t = 0; t < 2; t++) {
            int px = tile * 64 + wn * 16 + t * 8 + 2 * tig;
            float2 v0, v1;
            v0.x = acc[j][t][0]; v0.y = acc[j][t][1];
            v1.x = acc[j][t][2]; v1.y = acc[j][t][3];
            *reinterpret_cast<float2*>(out + ((size_t)n * COUT + r0) * HW + px) = v0;
            *reinterpret_cast<float2*>(out + ((size_t)n * COUT + r1) * HW + px) = v1;
        }
    }
}

// ---------------------------------------------------------------------------
extern "C" void kernel_launch(void* const* d_in, const int* in_sizes, int n_in,
                              void* d_out, int out_size)
{
    const float* x        = (const float*)d_in[0];
    const float* w1       = (const float*)d_in[1];
    const float* scale1   = (const float*)d_in[2];
    const float* shift1   = (const float*)d_in[3];
    const float* w2       = (const float*)d_in[4];
    const float* scale2   = (const float*)d_in[5];
    const float* shift2   = (const float*)d_in[6];
    const float* w3       = (const float*)d_in[7];
    const float* scale3   = (const float*)d_in[8];
    const float* shift3   = (const float*)d_in[9];
    const float* wsc      = (const float*)d_in[10];
    const float* scale_sc = (const float*)d_in[11];
    const float* shift_sc = (const float*)d_in[12];
    float* out = (float*)d_out;

    cudaFuncSetAttribute(k3_fused, cudaFuncAttributeMaxDynamicSharedMemorySize, SMEM_K3);

    prep_w<<<(14400 + 2880 + 1440 + 255) / 256, 256>>>(wsc, w3, w1, scale_sc, scale3, scale1);
    prep_x<<<(NB * 120 * 784) / 256, 256>>>(x);
    zero_pad<<<(NB * 12 * 784) / 256, 256>>>();
    k1_mma<<<dim3(49, 3, 32), 128>>>(shift1);
    k2_dw<<<(NB * 60 * 784) / 256, 256>>>(w2, scale2, shift2);
    k3_fused<<<dim3(49, 3, 32), 256, SMEM_K3>>>(shift3, shift_sc, out);
}